// round 2
// baseline (speedup 1.0000x reference)
#include <cuda_runtime.h>
#include <math.h>
#include <stdint.h>

// Problem shapes (fixed by setup_inputs)
#define NCELL 128   // NC
#define NCn   64    // Nc (neurons per cell)
#define DN    64    // Dn
#define AA    4     // A (ports)
#define HM    128   // MLP hidden
#define TT    16    // T
#define BB    8     // B
#define SR    68    // padded row stride for 64-wide matrices (bank-conflict avoidance)
#define SR2   132   // padded row stride for 128-wide matrices
#define NTHR  256

// ---- shared memory layout (in floats) ----
#define OFF_H    0
#define OFF_HEB  (OFF_H   + 64*SR)
#define OFF_W    (OFF_HEB + 64*SR)
#define OFF_M    (OFF_W   + 64*SR)
#define OFF_NID  (OFF_M   + 64*SR)
#define OFF_W1   (OFF_NID + 64*SR)     // msg_w1 [128][SR]
#define OFF_W2   (OFF_W1  + 128*SR)    // msg_w2 [64][SR2]
#define OFF_SCR  (OFF_W2  + 64*SR2)    // union: Wf [64][SR] during GEMM, hid [64][SR2] during MLP
#define OFF_XT   (OFF_SCR + 64*SR2)
#define OFF_INJ  (OFF_XT  + 64)
#define OFF_G    (OFF_INJ + 256)
#define OFF_HG   (OFF_G   + 64)
#define OFF_WG   (OFF_HG  + 64)
#define OFF_B1   (OFF_WG  + 64)
#define OFF_B2   (OFF_B1  + 128)
#define OFF_IP   (OFF_B2  + 64)        // 8 ints (4 input ports, 4 output ports)
#define SMEM_FLOATS (OFF_IP + 8)       // 48072 floats = 192288 bytes

__device__ __forceinline__ float sigf(float x) { return 1.0f / (1.0f + expf(-x)); }

__global__ void __launch_bounds__(NTHR, 1)
memgraph_kernel(const float* __restrict__ x,
                const float* __restrict__ h0,
                const float* __restrict__ W0,
                const float* __restrict__ heb0,
                const float* __restrict__ neuron_id,
                const float* __restrict__ msg_w1,
                const float* __restrict__ msg_b1,
                const float* __restrict__ msg_w2,
                const float* __restrict__ msg_b2,
                const float* __restrict__ inject_w,
                const float* __restrict__ inject_b,
                const float* __restrict__ Wdl,
                const float* __restrict__ dgl,
                const float* __restrict__ hdl,
                const int*   __restrict__ ipi,
                const int*   __restrict__ opi,
                float* __restrict__ out)
{
    extern __shared__ float sm[];
    float* sH   = sm + OFF_H;
    float* sHeb = sm + OFF_HEB;
    float* sW   = sm + OFF_W;
    float* sM   = sm + OFF_M;
    float* sNid = sm + OFF_NID;
    float* sW1  = sm + OFF_W1;
    float* sW2  = sm + OFF_W2;
    float* sScr = sm + OFF_SCR;
    float* sXt  = sm + OFF_XT;
    float* sInj = sm + OFF_INJ;
    float* sG   = sm + OFF_G;
    float* sHg  = sm + OFF_HG;
    float* sWg  = sm + OFF_WG;
    float* sB1  = sm + OFF_B1;
    float* sB2  = sm + OFF_B2;
    int*   sIP  = (int*)(sm + OFF_IP);

    const int tid = threadIdx.x;
    const int bc  = blockIdx.x;
    const int b   = bc / NCELL;
    const int c   = bc % NCELL;

    // ---- load state + constants into shared ----
    const size_t base4 = (size_t)bc * (64 * 64);
    for (int idx = tid; idx < 4096; idx += NTHR) {
        int i = idx >> 6, j = idx & 63;
        sH  [i * SR + j] = h0  [base4 + idx];
        sHeb[i * SR + j] = heb0[base4 + idx];
        sW  [i * SR + j] = W0  [base4 + idx];
        sNid[i * SR + j] = neuron_id[(size_t)c * 4096 + idx];
    }
    for (int idx = tid; idx < HM * DN; idx += NTHR)
        sW1[(idx >> 6) * SR + (idx & 63)] = msg_w1[idx];
    for (int idx = tid; idx < DN * HM; idx += NTHR)
        sW2[(idx >> 7) * SR2 + (idx & 127)] = msg_w2[idx];
    if (tid < HM) sB1[tid] = msg_b1[tid];
    if (tid < 64) {
        sB2[tid] = msg_b2[tid];
        sG [tid] = 0.5f * sigf(dgl[c * 64 + tid]);          // gamma
        sHg[tid] = 0.5f * sigf(hdl[c * 64 + tid]);          // hebbian gate
        sWg[tid] = 1.0f - 0.5f * sigf(Wdl[c * 64 + tid]);   // (1 - wg)
    }
    if (tid < AA) {
        sIP[tid]     = ipi[c * AA + tid];
        sIP[4 + tid] = opi[c * AA + tid];
    }
    __syncthreads();

    const int ti = tid >> 4;   // 0..15 (row tile)
    const int tj = tid & 15;   // 0..15 (col tile)

    for (int t = 0; t < TT; ++t) {
        // ---- A: load xt, compute injection inj[a][d] ----
        if (tid < 64)
            sXt[tid] = x[(((size_t)b * TT + t) * NCELL + c) * 64 + tid];
        __syncthreads();
        {
            int aa = tid >> 6, d = tid & 63;
            int row = aa * 64 + d;
            const float4* wr  = (const float4*)(inject_w + ((size_t)c * 256 + row) * 64);
            const float4* xt4 = (const float4*)sXt;
            float s = inject_b[c * 256 + row];
            #pragma unroll
            for (int k = 0; k < 16; ++k) {
                float4 w = __ldg(wr + k);
                float4 xv = xt4[k];
                s += w.x * xv.x + w.y * xv.y + w.z * xv.z + w.w * xv.w;
            }
            sInj[tid] = s;
        }
        __syncthreads();

        // ---- Wf = W + heb (into scratch); scatter inj onto input ports of h ----
        for (int idx = tid; idx < 4096; idx += NTHR) {
            int i = idx >> 6, j = idx & 63;
            sScr[i * SR + j] = sW[i * SR + j] + sHeb[i * SR + j];
        }
        if (tid < 64) {
            // one thread per column d: sequential += handles duplicate ports deterministically
            #pragma unroll
            for (int aa = 0; aa < AA; ++aa)
                sH[sIP[aa] * SR + tid] += sInj[aa * 64 + tid];
        }
        __syncthreads();

        // ---- B: m = Wf @ h_in   (64x64 @ 64x64) ----
        {
            float acc[4][4] = {};
            #pragma unroll 4
            for (int j4 = 0; j4 < 16; ++j4) {
                float4 hv0 = *(const float4*)&sH[(j4 * 4 + 0) * SR + tj * 4];
                float4 hv1 = *(const float4*)&sH[(j4 * 4 + 1) * SR + tj * 4];
                float4 hv2 = *(const float4*)&sH[(j4 * 4 + 2) * SR + tj * 4];
                float4 hv3 = *(const float4*)&sH[(j4 * 4 + 3) * SR + tj * 4];
                #pragma unroll
                for (int ii = 0; ii < 4; ++ii) {
                    float4 wv = *(const float4*)&sScr[(ti * 4 + ii) * SR + j4 * 4];
                    acc[ii][0] += wv.x * hv0.x + wv.y * hv1.x + wv.z * hv2.x + wv.w * hv3.x;
                    acc[ii][1] += wv.x * hv0.y + wv.y * hv1.y + wv.z * hv2.y + wv.w * hv3.y;
                    acc[ii][2] += wv.x * hv0.z + wv.y * hv1.z + wv.z * hv2.z + wv.w * hv3.z;
                    acc[ii][3] += wv.x * hv0.w + wv.y * hv1.w + wv.z * hv2.w + wv.w * hv3.w;
                }
            }
            #pragma unroll
            for (int ii = 0; ii < 4; ++ii)
                *(float4*)&sM[(ti * 4 + ii) * SR + tj * 4] =
                    make_float4(acc[ii][0], acc[ii][1], acc[ii][2], acc[ii][3]);
        }
        __syncthreads();

        // ---- C1: hid = tanh(m @ w1^T + b1)   (64x64 @ 64x128) ----
        {
            float acc[4][8] = {};
            #pragma unroll 2
            for (int k4 = 0; k4 < 16; ++k4) {
                float4 mv[4];
                #pragma unroll
                for (int ii = 0; ii < 4; ++ii)
                    mv[ii] = *(const float4*)&sM[(ti * 4 + ii) * SR + k4 * 4];
                #pragma unroll
                for (int jj = 0; jj < 8; ++jj) {
                    float4 wv = *(const float4*)&sW1[(tj * 8 + jj) * SR + k4 * 4];
                    #pragma unroll
                    for (int ii = 0; ii < 4; ++ii)
                        acc[ii][jj] += mv[ii].x * wv.x + mv[ii].y * wv.y
                                     + mv[ii].z * wv.z + mv[ii].w * wv.w;
                }
            }
            #pragma unroll
            for (int ii = 0; ii < 4; ++ii)
                #pragma unroll
                for (int jj = 0; jj < 8; ++jj)
                    sScr[(ti * 4 + ii) * SR2 + tj * 8 + jj] =
                        tanhf(acc[ii][jj] + sB1[tj * 8 + jj]);
        }
        __syncthreads();

        // ---- C2: out = hid @ w2^T + b2; gated state update ----
        {
            float acc[4][4] = {};
            #pragma unroll 2
            for (int k4 = 0; k4 < 32; ++k4) {
                float4 hv[4];
                #pragma unroll
                for (int ii = 0; ii < 4; ++ii)
                    hv[ii] = *(const float4*)&sScr[(ti * 4 + ii) * SR2 + k4 * 4];
                #pragma unroll
                for (int jj = 0; jj < 4; ++jj) {
                    float4 wv = *(const float4*)&sW2[(tj * 4 + jj) * SR2 + k4 * 4];
                    #pragma unroll
                    for (int ii = 0; ii < 4; ++ii)
                        acc[ii][jj] += hv[ii].x * wv.x + hv[ii].y * wv.y
                                     + hv[ii].z * wv.z + hv[ii].w * wv.w;
                }
            }
            #pragma unroll
            for (int ii = 0; ii < 4; ++ii) {
                int r = ti * 4 + ii;
                float g = sG[r];
                #pragma unroll
                for (int jj = 0; jj < 4; ++jj) {
                    int d = tj * 4 + jj;
                    float mm = acc[ii][jj] + sB2[d];
                    float hin = sH[r * SR + d];
                    sH[r * SR + d] = (1.0f - g) * hin + g * tanhf(mm + sNid[r * SR + d]);
                }
            }
        }
        __syncthreads();

        // ---- D: hebbian outer-product update + W decay ----
        {
            float acc[4][4] = {};
            #pragma unroll 4
            for (int d4 = 0; d4 < 16; ++d4) {
                float4 u[4], v[4];
                #pragma unroll
                for (int ii = 0; ii < 4; ++ii)
                    u[ii] = *(const float4*)&sH[(ti * 4 + ii) * SR + d4 * 4];
                #pragma unroll
                for (int jj = 0; jj < 4; ++jj)
                    v[jj] = *(const float4*)&sH[(tj * 4 + jj) * SR + d4 * 4];
                #pragma unroll
                for (int ii = 0; ii < 4; ++ii)
                    #pragma unroll
                    for (int jj = 0; jj < 4; ++jj)
                        acc[ii][jj] += u[ii].x * v[jj].x + u[ii].y * v[jj].y
                                     + u[ii].z * v[jj].z + u[ii].w * v[jj].w;
            }
            #pragma unroll
            for (int ii = 0; ii < 4; ++ii) {
                int i = ti * 4 + ii;
                float hg1 = 1.0f - sHg[i];
                float hgs = sHg[i] * (1.0f / 64.0f);   // (Dn^-0.5)^2 folded in
                float wgd = sWg[i];
                #pragma unroll
                for (int jj = 0; jj < 4; ++jj) {
                    int j = tj * 4 + jj;
                    float nh = hg1 * sHeb[i * SR + j] + hgs * acc[ii][jj];
                    sHeb[i * SR + j] = (i == j) ? 0.0f : nh;
                    sW[i * SR + j] *= wgd;
                }
            }
        }

        // ---- readout from output ports (h already synced after C2) ----
        if (tid < 64) {
            float s = 0.0f;
            #pragma unroll
            for (int aa = 0; aa < AA; ++aa)
                s += sH[sIP[4 + aa] * SR + tid];
            // mean over A (=/4) * readout_scale (A^-0.5 = 0.5) -> 0.125
            out[(((size_t)b * TT + t) * NCELL + c) * 64 + tid] = 0.125f * s;
        }
        __syncthreads();
    }
}

extern "C" void kernel_launch(void* const* d_in, const int* in_sizes, int n_in,
                              void* d_out, int out_size)
{
    (void)in_sizes; (void)n_in; (void)out_size;
    const float* x         = (const float*)d_in[0];
    const float* h0        = (const float*)d_in[1];
    const float* W0        = (const float*)d_in[2];
    const float* heb0      = (const float*)d_in[3];
    const float* neuron_id = (const float*)d_in[4];
    const float* msg_w1    = (const float*)d_in[5];
    const float* msg_b1    = (const float*)d_in[6];
    const float* msg_w2    = (const float*)d_in[7];
    const float* msg_b2    = (const float*)d_in[8];
    const float* inject_w  = (const float*)d_in[9];
    const float* inject_b  = (const float*)d_in[10];
    const float* Wdl       = (const float*)d_in[11];
    const float* dgl       = (const float*)d_in[12];
    const float* hdl       = (const float*)d_in[13];
    const int*   ipi       = (const int*)d_in[14];
    const int*   opi       = (const int*)d_in[15];
    float* out = (float*)d_out;

    size_t smem_bytes = (size_t)SMEM_FLOATS * sizeof(float);
    cudaFuncSetAttribute(memgraph_kernel,
                         cudaFuncAttributeMaxDynamicSharedMemorySize,
                         (int)smem_bytes);

    memgraph_kernel<<<BB * NCELL, NTHR, smem_bytes>>>(
        x, h0, W0, heb0, neuron_id, msg_w1, msg_b1, msg_w2, msg_b2,
        inject_w, inject_b, Wdl, dgl, hdl, ipi, opi, out);
}

// round 6
// speedup vs baseline: 2.1849x; 2.1849x over previous
#include <cuda_runtime.h>
#include <math.h>
#include <stdint.h>

// Problem shapes (fixed by setup_inputs)
#define NCELL 128
#define DN    64
#define AA    4
#define HM    128
#define TT    16
#define BB    8
#define SR    68    // row stride for 64-wide fp32 tiles (68 mod 32 = 4 banks)
#define W1TS  132   // w1T [64 k][132]  (132 mod 32 = 4)
#define W2TS  68    // w2T [128 hm][68]
#define NTHR  512

// ---- shared memory layout (floats). per-cell buffers are 2 x 4352 ----
#define F_H     0
#define F_HEB   8704
#define F_M     17408
#define F_H2    26112   // union: W0 staging, then hid half-buffer
#define F_W1T   34816   // 64*132  = 8448
#define F_W2T   43264   // 128*68  = 8704
#define F_XT    51968   // 2 x 64
#define F_INJ   52096   // 2 x 256
#define F_G     52608   // 2 x 64
#define F_HG    52736
#define F_WG1M  52864   // (1 - wg)
#define F_DF    52992   // running decay product
#define F_B1    53120   // 128
#define F_B2    53248   // 64
#define F_IP    53312   // 2 x 8 ints
#define SMEMF   53328   // 213,312 bytes

#define HBAR() asm volatile("bar.sync %0, %1;" :: "r"(hf + 1), "n"(256) : "memory")

__device__ __forceinline__ float sigf(float x) { return 1.0f / (1.0f + expf(-x)); }

// hid_half[i][u] = tanh( sum_k m[i][k] * w1T[k][h0+u] + b1[h0+u] ), u = tj*4..+3
__device__ __forceinline__ void mlp1_half(const float* __restrict__ sMloc,
                                          const float* __restrict__ sW1T,
                                          const float* __restrict__ sB1,
                                          float* __restrict__ sH2loc,
                                          int ti, int tj, int h0)
{
    float acc[4][4] = {};
    #pragma unroll 2
    for (int k4 = 0; k4 < 16; ++k4) {
        float4 wA = *(const float4*)&sW1T[(k4 * 4 + 0) * W1TS + h0 + tj * 4];
        float4 wB = *(const float4*)&sW1T[(k4 * 4 + 1) * W1TS + h0 + tj * 4];
        float4 wC = *(const float4*)&sW1T[(k4 * 4 + 2) * W1TS + h0 + tj * 4];
        float4 wD = *(const float4*)&sW1T[(k4 * 4 + 3) * W1TS + h0 + tj * 4];
        #pragma unroll
        for (int ii = 0; ii < 4; ++ii) {
            float4 mv = *(const float4*)&sMloc[(ti * 4 + ii) * SR + k4 * 4];
            acc[ii][0] += mv.x * wA.x + mv.y * wB.x + mv.z * wC.x + mv.w * wD.x;
            acc[ii][1] += mv.x * wA.y + mv.y * wB.y + mv.z * wC.y + mv.w * wD.y;
            acc[ii][2] += mv.x * wA.z + mv.y * wB.z + mv.z * wC.z + mv.w * wD.z;
            acc[ii][3] += mv.x * wA.w + mv.y * wB.w + mv.z * wC.w + mv.w * wD.w;
        }
    }
    float4 bv = *(const float4*)&sB1[h0 + tj * 4];
    #pragma unroll
    for (int ii = 0; ii < 4; ++ii) {
        float4 o;
        o.x = tanhf(acc[ii][0] + bv.x);
        o.y = tanhf(acc[ii][1] + bv.y);
        o.z = tanhf(acc[ii][2] + bv.z);
        o.w = tanhf(acc[ii][3] + bv.w);
        *(float4*)&sH2loc[(ti * 4 + ii) * SR + tj * 4] = o;
    }
}

// acc2[ii][d] += sum_u hid[i][u] * w2T[h0+u][d], d = tj*4..+3
__device__ __forceinline__ void mlp2_half(const float* __restrict__ sH2loc,
                                          const float* __restrict__ sW2T,
                                          float acc[4][4], int ti, int tj, int h0)
{
    #pragma unroll 2
    for (int u4 = 0; u4 < 16; ++u4) {
        float4 wA = *(const float4*)&sW2T[(h0 + u4 * 4 + 0) * W2TS + tj * 4];
        float4 wB = *(const float4*)&sW2T[(h0 + u4 * 4 + 1) * W2TS + tj * 4];
        float4 wC = *(const float4*)&sW2T[(h0 + u4 * 4 + 2) * W2TS + tj * 4];
        float4 wD = *(const float4*)&sW2T[(h0 + u4 * 4 + 3) * W2TS + tj * 4];
        #pragma unroll
        for (int ii = 0; ii < 4; ++ii) {
            float4 hv = *(const float4*)&sH2loc[(ti * 4 + ii) * SR + u4 * 4];
            acc[ii][0] += hv.x * wA.x + hv.y * wB.x + hv.z * wC.x + hv.w * wD.x;
            acc[ii][1] += hv.x * wA.y + hv.y * wB.y + hv.z * wC.y + hv.w * wD.y;
            acc[ii][2] += hv.x * wA.z + hv.y * wB.z + hv.z * wC.z + hv.w * wD.z;
            acc[ii][3] += hv.x * wA.w + hv.y * wB.w + hv.z * wC.w + hv.w * wD.w;
        }
    }
}

__global__ void __launch_bounds__(NTHR, 1)
memgraph_kernel(const float* __restrict__ x,
                const float* __restrict__ h0,
                const float* __restrict__ W0,
                const float* __restrict__ heb0,
                const float* __restrict__ neuron_id,
                const float* __restrict__ msg_w1,
                const float* __restrict__ msg_b1,
                const float* __restrict__ msg_w2,
                const float* __restrict__ msg_b2,
                const float* __restrict__ inject_w,
                const float* __restrict__ inject_b,
                const float* __restrict__ Wdl,
                const float* __restrict__ dgl,
                const float* __restrict__ hdl,
                const int*   __restrict__ ipi,
                const int*   __restrict__ opi,
                float* __restrict__ out)
{
    extern __shared__ float sm[];

    const int tid  = threadIdx.x;
    const int hf   = tid >> 8;
    const int htid = tid & 255;

    const int blk = blockIdx.x;
    const int b   = blk >> 6;
    const int c   = (blk & 63) * 2 + hf;
    const int bc  = b * NCELL + c;

    float* sH   = sm + F_H   + hf * 4352;
    float* sHeb = sm + F_HEB + hf * 4352;
    float* sM   = sm + F_M   + hf * 4352;
    float* sH2  = sm + F_H2  + hf * 4352;   // W0 staging / hid half
    float* sW1T = sm + F_W1T;
    float* sW2T = sm + F_W2T;
    float* sXt  = sm + F_XT  + hf * 64;
    float* sInj = sm + F_INJ + hf * 256;
    float* sG   = sm + F_G    + hf * 64;
    float* sHg  = sm + F_HG   + hf * 64;
    float* sWg1 = sm + F_WG1M + hf * 64;
    float* sDf  = sm + F_DF   + hf * 64;
    float* sB1  = sm + F_B1;
    float* sB2  = sm + F_B2;
    int*   sIP  = (int*)(sm + F_IP) + hf * 8;

    // ---- init: shared transposed weights (whole block) ----
    for (int idx = tid; idx < HM * DN; idx += NTHR) {
        int hm = idx & 127, k = idx >> 7;
        sW1T[k * W1TS + hm] = msg_w1[hm * 64 + k];       // w1T[k][hm]
    }
    for (int idx = tid; idx < DN * HM; idx += NTHR) {
        int d = idx & 63, hm = idx >> 6;
        sW2T[hm * W2TS + d] = msg_w2[d * 128 + hm];      // w2T[hm][d]
    }
    if (tid < HM) sB1[tid] = msg_b1[tid];
    if (tid < 64) sB2[tid] = msg_b2[tid];

    // ---- init: per-cell state ----
    const size_t base4 = (size_t)bc * 4096;
    for (int idx = htid; idx < 4096; idx += 256) {
        int i = idx >> 6, j = idx & 63;
        sH  [i * SR + j] = h0  [base4 + idx];
        sHeb[i * SR + j] = heb0[base4 + idx];
    }
    if (htid < 64) {
        sG  [htid] = 0.5f * sigf(dgl[c * 64 + htid]);
        sHg [htid] = 0.5f * sigf(hdl[c * 64 + htid]);
        sWg1[htid] = 1.0f - 0.5f * sigf(Wdl[c * 64 + htid]);
        sDf [htid] = 1.0f;
        sXt [htid] = x[(((size_t)b * TT + 0) * NCELL + c) * 64 + htid];   // t=0
    }
    if (htid < AA) {
        sIP[htid]     = ipi[c * AA + htid];
        sIP[4 + htid] = opi[c * AA + htid];
    }
    __syncthreads();

    const int ti = htid >> 4;
    const int tj = htid & 15;
    const float* Wbase = W0 + base4;

    for (int t = 0; t < TT; ++t) {
        // ---- P0: stage W0 -> sH2 (coalesced); A: injection ----
        #pragma unroll
        for (int it = 0; it < 4; ++it) {
            int i = it * 16 + ti;
            float4 w = __ldg((const float4*)(Wbase + i * 64 + tj * 4));
            *(float4*)&sH2[i * SR + tj * 4] = w;
        }
        {
            int aa = htid >> 6, d = htid & 63;
            int row = aa * 64 + d;
            const float4* wr  = (const float4*)(inject_w + ((size_t)c * 256 + row) * 64);
            const float4* xt4 = (const float4*)sXt;
            float s = inject_b[c * 256 + row];
            #pragma unroll 4
            for (int k = 0; k < 16; ++k) {
                float4 w = __ldg(wr + k);
                float4 xv = xt4[k];
                s += w.x * xv.x + w.y * xv.y + w.z * xv.z + w.w * xv.w;
            }
            sInj[htid] = s;
        }
        HBAR();

        // ---- scatter inj onto input ports of h (sequential -> deterministic) ----
        if (htid < 64) {
            #pragma unroll
            for (int aa = 0; aa < AA; ++aa)
                sH[sIP[aa] * SR + htid] += sInj[aa * 64 + htid];
        }
        HBAR();

        // ---- B: m = (df*W0 + heb) @ h_in ----
        {
            float dfr[4];
            #pragma unroll
            for (int ii = 0; ii < 4; ++ii) dfr[ii] = sDf[ti * 4 + ii];
            float acc[4][4] = {};
            #pragma unroll 2
            for (int j4 = 0; j4 < 16; ++j4) {
                float4 hv0 = *(const float4*)&sH[(j4 * 4 + 0) * SR + tj * 4];
                float4 hv1 = *(const float4*)&sH[(j4 * 4 + 1) * SR + tj * 4];
                float4 hv2 = *(const float4*)&sH[(j4 * 4 + 2) * SR + tj * 4];
                float4 hv3 = *(const float4*)&sH[(j4 * 4 + 3) * SR + tj * 4];
                #pragma unroll
                for (int ii = 0; ii < 4; ++ii) {
                    float4 wv = *(const float4*)&sH2 [(ti * 4 + ii) * SR + j4 * 4];
                    float4 bv = *(const float4*)&sHeb[(ti * 4 + ii) * SR + j4 * 4];
                    float fx = fmaf(wv.x, dfr[ii], bv.x);
                    float fy = fmaf(wv.y, dfr[ii], bv.y);
                    float fz = fmaf(wv.z, dfr[ii], bv.z);
                    float fw = fmaf(wv.w, dfr[ii], bv.w);
                    acc[ii][0] += fx * hv0.x + fy * hv1.x + fz * hv2.x + fw * hv3.x;
                    acc[ii][1] += fx * hv0.y + fy * hv1.y + fz * hv2.y + fw * hv3.y;
                    acc[ii][2] += fx * hv0.z + fy * hv1.z + fz * hv2.z + fw * hv3.z;
                    acc[ii][3] += fx * hv0.w + fy * hv1.w + fz * hv2.w + fw * hv3.w;
                }
            }
            #pragma unroll
            for (int ii = 0; ii < 4; ++ii)
                *(float4*)&sM[(ti * 4 + ii) * SR + tj * 4] =
                    make_float4(acc[ii][0], acc[ii][1], acc[ii][2], acc[ii][3]);
        }
        HBAR();

        // ---- C1a / C2a / C1b / C2b: shared MLP in two hm-halves ----
        float acc2[4][4] = {};
        mlp1_half(sM, sW1T, sB1, sH2, ti, tj, 0);     // overwrites W0 staging (dead)
        HBAR();
        mlp2_half(sH2, sW2T, acc2, ti, tj, 0);
        HBAR();
        mlp1_half(sM, sW1T, sB1, sH2, ti, tj, 64);
        HBAR();
        mlp2_half(sH2, sW2T, acc2, ti, tj, 64);

        // ---- gated h update ----
        {
            float4 bv = *(const float4*)&sB2[tj * 4];
            #pragma unroll
            for (int ii = 0; ii < 4; ++ii) {
                int r = ti * 4 + ii;
                float4 nv = __ldg((const float4*)(neuron_id + (size_t)c * 4096
                                                  + r * 64 + tj * 4));
                float g = sG[r];
                float* hr = &sH[r * SR + tj * 4];
                hr[0] = (1.0f - g) * hr[0] + g * tanhf(acc2[ii][0] + bv.x + nv.x);
                hr[1] = (1.0f - g) * hr[1] + g * tanhf(acc2[ii][1] + bv.y + nv.y);
                hr[2] = (1.0f - g) * hr[2] + g * tanhf(acc2[ii][2] + bv.z + nv.z);
                hr[3] = (1.0f - g) * hr[3] + g * tanhf(acc2[ii][3] + bv.w + nv.w);
            }
        }
        HBAR();

        // ---- D: hebbian outer product (j = tj + 16*jj, conflict-free) ----
        {
            float acc[4][4] = {};
            #pragma unroll 2
            for (int d4 = 0; d4 < 16; ++d4) {
                float4 v[4];
                #pragma unroll
                for (int jj = 0; jj < 4; ++jj)
                    v[jj] = *(const float4*)&sH[(tj + 16 * jj) * SR + d4 * 4];
                #pragma unroll
                for (int ii = 0; ii < 4; ++ii) {
                    float4 u = *(const float4*)&sH[(ti * 4 + ii) * SR + d4 * 4];
                    #pragma unroll
                    for (int jj = 0; jj < 4; ++jj)
                        acc[ii][jj] += u.x * v[jj].x + u.y * v[jj].y
                                     + u.z * v[jj].z + u.w * v[jj].w;
                }
            }
            #pragma unroll
            for (int ii = 0; ii < 4; ++ii) {
                int i = ti * 4 + ii;
                float hg1 = 1.0f - sHg[i];
                float hgs = sHg[i] * (1.0f / 64.0f);
                #pragma unroll
                for (int jj = 0; jj < 4; ++jj) {
                    int j = tj + 16 * jj;
                    float nh = hg1 * sHeb[i * SR + j] + hgs * acc[ii][jj];
                    sHeb[i * SR + j] = (i == j) ? 0.0f : nh;
                }
            }
        }

        // ---- readout / decay update / prefetch next xt (disjoint thread sets) ----
        if (htid < 64) {
            float s = 0.0f;
            #pragma unroll
            for (int aa = 0; aa < AA; ++aa)
                s += sH[sIP[4 + aa] * SR + htid];
            out[(((size_t)b * TT + t) * NCELL + c) * 64 + htid] = 0.125f * s;
        } else if (htid < 128) {
            sDf[htid - 64] *= sWg1[htid - 64];
        } else if (htid >= 192 && t + 1 < TT) {
            sXt[htid - 192] = x[(((size_t)b * TT + t + 1) * NCELL + c) * 64 + (htid - 192)];
        }
        HBAR();
    }
}

extern "C" void kernel_launch(void* const* d_in, const int* in_sizes, int n_in,
                              void* d_out, int out_size)
{
    (void)in_sizes; (void)n_in; (void)out_size;
    const float* x         = (const float*)d_in[0];
    const float* h0        = (const float*)d_in[1];
    const float* W0        = (const float*)d_in[2];
    const float* heb0      = (const float*)d_in[3];
    const float* neuron_id = (const float*)d_in[4];
    const float* msg_w1    = (const float*)d_in[5];
    const float* msg_b1    = (const float*)d_in[6];
    const float* msg_w2    = (const float*)d_in[7];
    const float* msg_b2    = (const float*)d_in[8];
    const float* inject_w  = (const float*)d_in[9];
    const float* inject_b  = (const float*)d_in[10];
    const float* Wdl       = (const float*)d_in[11];
    const float* dgl       = (const float*)d_in[12];
    const float* hdl       = (const float*)d_in[13];
    const int*   ipi       = (const int*)d_in[14];
    const int*   opi       = (const int*)d_in[15];
    float* out = (float*)d_out;

    size_t smem_bytes = (size_t)SMEMF * sizeof(float);   // 213,312 B
    cudaFuncSetAttribute(memgraph_kernel,
                         cudaFuncAttributeMaxDynamicSharedMemorySize,
                         (int)smem_bytes);

    memgraph_kernel<<<(BB * NCELL) / 2, NTHR, smem_bytes>>>(
        x, h0, W0, heb0, neuron_id, msg_w1, msg_b1, msg_w2, msg_b2,
        inject_w, inject_b, Wdl, dgl, hdl, ipi, opi, out);
}